// round 14
// baseline (speedup 1.0000x reference)
#include <cuda_runtime.h>
#include <cuda_bf16.h>
#include <math.h>
#include <stdint.h>

// ---------------------------------------------------------------------------
// Problem constants
// ---------------------------------------------------------------------------
#define BATCH 4
#define C_DIM 1024
#define CI_DIM 512
#define T_DIM 16
#define H_DIM 28
#define W_DIM 28
#define NPOS (T_DIM * H_DIM * W_DIM)   // 12544
#define TP 8
#define HP 14
#define WP 14
#define MPOS (TP * HP * WP)            // 1568
#define MPAD 1792                      // 14 * 128 (divisible by 256)

typedef __nv_bfloat16 bf16;

// ---------------------------------------------------------------------------
// Scratch (device globals; zero-initialized at load — pad regions never written)
// ---------------------------------------------------------------------------
__device__ bf16  d_xT  [(size_t)BATCH * NPOS * C_DIM];    // x^T  (B,N,C)
__device__ bf16  d_wbuf[(size_t)4 * CI_DIM * C_DIM];      // bf16 weights
__device__ bf16  d_theta[(size_t)BATCH * NPOS * CI_DIM];  // theta (B,N,Ci)
__device__ bf16  d_scr [(size_t)BATCH * NPOS * CI_DIM];   // conv scratch
__device__ bf16  d_phi [(size_t)BATCH * MPAD * CI_DIM];   // phi pooled, M-padded
__device__ bf16  d_gmc [(size_t)BATCH * MPOS * CI_DIM];   // g pooled (B,M,Ci)
__device__ bf16  d_gcm [(size_t)BATCH * CI_DIM * MPAD];   // g pooled^T, M-padded
__device__ bf16  d_fbuf[(size_t)BATCH * NPOS * MPAD];     // logits->probs bf16
__device__ bf16  d_ybuf[(size_t)BATCH * NPOS * CI_DIM];   // y (B,N,Ci)

// ---------------------------------------------------------------------------
// PTX helpers (legacy tensor path — compute_103-safe)
// ---------------------------------------------------------------------------
__device__ __forceinline__ uint32_t smem_u32(const void* p) {
    return (uint32_t)__cvta_generic_to_shared(p);
}
__device__ __forceinline__ void ldmatrix_x4(uint32_t* r, uint32_t addr) {
    asm volatile("ldmatrix.sync.aligned.m8n8.x4.shared.b16 {%0,%1,%2,%3}, [%4];"
                 : "=r"(r[0]), "=r"(r[1]), "=r"(r[2]), "=r"(r[3]) : "r"(addr));
}
__device__ __forceinline__ void mma_16816(float* c, const uint32_t* a, const uint32_t* b) {
    asm volatile("mma.sync.aligned.m16n8k16.row.col.f32.bf16.bf16.f32 "
                 "{%0,%1,%2,%3}, {%4,%5,%6,%7}, {%8,%9}, {%0,%1,%2,%3};"
                 : "+f"(c[0]), "+f"(c[1]), "+f"(c[2]), "+f"(c[3])
                 : "r"(a[0]), "r"(a[1]), "r"(a[2]), "r"(a[3]), "r"(b[0]), "r"(b[1]));
}
__device__ __forceinline__ void cp16(uint32_t s, const void* g) {
    asm volatile("cp.async.cg.shared.global [%0], [%1], 16;" :: "r"(s), "l"(g));
}
#define CP_COMMIT asm volatile("cp.async.commit_group;")
#define CP_WAIT0  asm volatile("cp.async.wait_group 0;")
#define CP_WAIT1  asm volatile("cp.async.wait_group 1;")
#define CP_WAIT2  asm volatile("cp.async.wait_group 2;")

// ---------------------------------------------------------------------------
// bf16 NT tensor-core GEMM: C(MxN) = A(MxK) * B(NxK)^T, K-contiguous inputs.
// CTA tile 128x256, warp tile 64x64 (8 warps), K chunks of 64, 4-stage
// cp.async ring (prefetch distance 3), one __syncthreads per chunk,
// padded-stride smem (144B rows: conflict-free cp.async + ldmatrix).
// Requires M%128==0, N%256==0, K%64==0.
// EPI 0: plain   EPI 1: + colBias[col]
// EPI 2: out = resid + gamma[row]/sqrt(1+eps)*(acc + rowBias[row]) + beta[row]
// ---------------------------------------------------------------------------
#define ROWB 144u                  // smem row stride bytes (64*2 + 16 pad)
#define AMATB (128u * ROWB)        // 18432 bytes (A: 128 rows)
#define BMATB (256u * ROWB)        // 36864 bytes (B: 256 rows)
#define STGB (AMATB + BMATB)       // 55296 bytes per stage
#define SMEM_MMA (4 * (int)STGB)   // 221184 bytes

template <int EPI, typename OutT>
__global__ void __launch_bounds__(256, 1)
mma_nt(const bf16* __restrict__ A, const bf16* __restrict__ B,
       OutT* __restrict__ C, int M, int N, int K,
       long sA, long sB, long sC,
       const float* __restrict__ colBias,
       const float* __restrict__ rowBias,
       const float* __restrict__ gamma,
       const float* __restrict__ beta,
       const float* __restrict__ resid, long sR) {
    extern __shared__ char smem[];
    const uint32_t sbase = smem_u32(smem);
    const int tid = threadIdx.x;
    const int lane = tid & 31;
    const int warp = tid >> 5;
    const int z = blockIdx.z;
    const int m0 = blockIdx.y * 128;
    const int n0 = blockIdx.x * 256;
    const int wm = (warp & 1) * 64;   // warp row offset (2 warps over M)
    const int wn = (warp >> 1) * 64;  // warp col offset (4 warps over N)

    const char* gA = (const char*)(A + (long)z * sA) + (long)m0 * K * 2;
    const char* gB = (const char*)(B + (long)z * sB) + (long)n0 * K * 2;
    const long strK = (long)K * 2;
    const int nCh = K >> 6;

    // staging: per chunk A = 1024 x 16B, B = 2048 x 16B; 256 threads x 12
    // t 0..3  -> A rows, t 4..11 -> B rows
    uint32_t soff[12];
    long goff[12];
#pragma unroll
    for (int t = 0; t < 12; t++) {
        const int idx = tid + t * 256;
        const int j = (t < 4) ? idx : (idx - 1024);
        const uint32_t base = (t < 4) ? 0u : AMATB;
        soff[t] = base + (uint32_t)(j >> 3) * ROWB + (uint32_t)(j & 7) * 16u;
        goff[t] = (long)(j >> 3) * strK + (long)(j & 7) * 16;
    }

#define LOAD_CHUNK(buf, ch)                                                   \
    {                                                                         \
        const long cb = (long)(ch) << 7;                                      \
        const uint32_t s0 = sbase + (uint32_t)(buf) * STGB;                   \
        _Pragma("unroll") for (int t = 0; t < 4; t++)                         \
            cp16(s0 + soff[t], gA + goff[t] + cb);                            \
        _Pragma("unroll") for (int t = 4; t < 12; t++)                        \
            cp16(s0 + soff[t], gB + goff[t] + cb);                            \
        CP_COMMIT;                                                            \
    }

    float acc[4][8][4] = {};

    LOAD_CHUNK(0, 0);
    if (nCh > 1) LOAD_CHUNK(1, 1);
    if (nCh > 2) LOAD_CHUNK(2, 2);

    for (int c = 0; c < nCh; ++c) {
        const int rem = nCh - 1 - c;
        if (rem >= 2) { CP_WAIT2; } else if (rem == 1) { CP_WAIT1; } else { CP_WAIT0; }
        __syncthreads();
        if (c + 3 < nCh) LOAD_CHUNK((c + 3) & 3, c + 3);
        const uint32_t sa = sbase + (uint32_t)(c & 3) * STGB;
        const uint32_t sb = sa + AMATB;
#pragma unroll
        for (int ks = 0; ks < 4; ++ks) {
            uint32_t afr[4][4], bfr[8][2];
#pragma unroll
            for (int mi = 0; mi < 4; mi++)
                ldmatrix_x4(afr[mi],
                    sa + (uint32_t)(wm + mi * 16 + (lane & 15)) * ROWB +
                         (uint32_t)ks * 32u + (uint32_t)(lane >> 4) * 16u);
#pragma unroll
            for (int nb = 0; nb < 4; nb++) {
                uint32_t bq[4];
                ldmatrix_x4(bq,
                    sb + (uint32_t)(wn + nb * 16 + (lane & 15)) * ROWB +
                         (uint32_t)ks * 32u + (uint32_t)(lane >> 4) * 16u);
                bfr[2 * nb + 0][0] = bq[0]; bfr[2 * nb + 0][1] = bq[2];
                bfr[2 * nb + 1][0] = bq[1]; bfr[2 * nb + 1][1] = bq[3];
            }
#pragma unroll
            for (int mi = 0; mi < 4; mi++)
#pragma unroll
                for (int ni = 0; ni < 8; ni++)
                    mma_16816(acc[mi][ni], afr[mi], bfr[ni]);
        }
    }

    // ---- epilogue ----
    const int tr = lane >> 2;
    const int tc = (lane & 3) * 2;
    const float bnscale = rsqrtf(1.0f + 1e-5f);
#pragma unroll
    for (int mi = 0; mi < 4; mi++) {
        const int r = m0 + wm + mi * 16 + tr;
#pragma unroll
        for (int ni = 0; ni < 8; ni++) {
            const int c = n0 + wn + ni * 8 + tc;
#pragma unroll
            for (int h = 0; h < 2; h++) {
                const int rr = r + h * 8;
                float v0 = acc[mi][ni][h * 2 + 0];
                float v1 = acc[mi][ni][h * 2 + 1];
                if (EPI == 1) {
                    v0 += colBias[c];
                    v1 += colBias[c + 1];
                } else if (EPI == 2) {
                    const float s = gamma[rr] * bnscale;
                    const float wb = rowBias[rr];
                    const float bt = beta[rr];
                    const float* rp = resid + (long)z * sR + (long)rr * N + c;
                    v0 = rp[0] + s * (v0 + wb) + bt;
                    v1 = rp[1] + s * (v1 + wb) + bt;
                }
                if constexpr (sizeof(OutT) == 2) {
                    __nv_bfloat162 p = __floats2bfloat162_rn(v0, v1);
                    *reinterpret_cast<__nv_bfloat162*>(
                        &((bf16*)(C + (long)z * sC))[(long)rr * N + c]) = p;
                } else {
                    float2 p = make_float2(v0, v1);
                    *reinterpret_cast<float2*>(
                        &((float*)(C + (long)z * sC))[(long)rr * N + c]) = p;
                }
            }
        }
    }
}

// ---------------------------------------------------------------------------
// Tiled transpose with dtype conversion: in (R,Cc) -> out (Cc,R) [ldOut], per z
// ---------------------------------------------------------------------------
__device__ __forceinline__ float ld_as_f(const float* p) { return *p; }
__device__ __forceinline__ float ld_as_f(const bf16* p) { return __bfloat162float(*p); }
__device__ __forceinline__ void st_from_f(float* p, float v) { *p = v; }
__device__ __forceinline__ void st_from_f(bf16* p, float v) { *p = __float2bfloat16(v); }

template <typename TI, typename TO>
__global__ void transpose_k(const TI* __restrict__ in, TO* __restrict__ out,
                            int R, int Cc, int ldOut, long sIn, long sOut) {
    __shared__ float tile[32][33];
    const TI* inb = in + (long)blockIdx.z * sIn;
    TO* outb = out + (long)blockIdx.z * sOut;
    const int c0 = blockIdx.x * 32;
    const int r0 = blockIdx.y * 32;
    const int tx = threadIdx.x, ty = threadIdx.y;
#pragma unroll
    for (int i = 0; i < 32; i += 8)
        tile[ty + i][tx] = ld_as_f(&inb[(long)(r0 + ty + i) * Cc + c0 + tx]);
    __syncthreads();
#pragma unroll
    for (int i = 0; i < 32; i += 8)
        st_from_f(&outb[(long)(c0 + ty + i) * ldOut + r0 + tx], tile[tx][ty + i]);
}

// ---------------------------------------------------------------------------
// fp32 -> bf16 elementwise convert
// ---------------------------------------------------------------------------
__global__ void f2bf_k(const float* __restrict__ in, bf16* __restrict__ out, int n) {
    const int i = blockIdx.x * 256 + threadIdx.x;
    if (i < n) out[i] = __float2bfloat16(in[i]);
}

// ---------------------------------------------------------------------------
// 2x2x2 max pool (bf16): conv (B,NPOS,Ci) -> out (B,outRows,Ci)
// ---------------------------------------------------------------------------
__global__ void pool_k(const bf16* __restrict__ conv, bf16* __restrict__ out,
                       int outRows) {
    const int ci = blockIdx.x * 256 + threadIdx.x;
    const int m = blockIdx.y;
    const int b = blockIdx.z;
    const int wp = m % WP;
    const int hp = (m / WP) % HP;
    const int tp = m / (WP * HP);
    const bf16* cb = conv + (long)b * NPOS * CI_DIM;
    const long n0 = (long)(2 * tp) * (H_DIM * W_DIM) + (long)(2 * hp) * W_DIM + 2 * wp;
    float mx = -INFINITY;
#pragma unroll
    for (int dt = 0; dt < 2; dt++)
#pragma unroll
        for (int dh = 0; dh < 2; dh++)
#pragma unroll
            for (int dw = 0; dw < 2; dw++) {
                long n = n0 + dt * (H_DIM * W_DIM) + dh * W_DIM + dw;
                mx = fmaxf(mx, __bfloat162float(cb[n * CI_DIM + ci]));
            }
    out[((long)b * outRows + m) * CI_DIM + ci] = __float2bfloat16(mx);
}

// ---------------------------------------------------------------------------
// In-place row softmax on bf16 logits (stride MPAD, MPOS valid); zeros the pads.
// ---------------------------------------------------------------------------
__global__ void __launch_bounds__(256) softmax_rows(bf16* __restrict__ f) {
    bf16* fr = f + (long)blockIdx.x * MPAD;
    const int t = threadIdx.x;
    float v[7];
    int cnt = 0;
    float mx = -1e30f;
    for (int i = t; i < MPOS; i += 256) {
        v[cnt] = __bfloat162float(fr[i]);
        mx = fmaxf(mx, v[cnt]);
        cnt++;
    }
    __shared__ float sred[8];
#pragma unroll
    for (int o = 16; o; o >>= 1) mx = fmaxf(mx, __shfl_xor_sync(0xffffffffu, mx, o));
    if ((t & 31) == 0) sred[t >> 5] = mx;
    __syncthreads();
    if (t < 32) {
        float m2 = (t < 8) ? sred[t] : -1e30f;
#pragma unroll
        for (int o = 4; o; o >>= 1) m2 = fmaxf(m2, __shfl_xor_sync(0xffffffffu, m2, o));
        if (t == 0) sred[0] = m2;
    }
    __syncthreads();
    mx = sred[0];
    float sum = 0.f;
    for (int j = 0; j < cnt; j++) {
        v[j] = __expf(v[j] - mx);
        sum += v[j];
    }
    __syncthreads();
#pragma unroll
    for (int o = 16; o; o >>= 1) sum += __shfl_xor_sync(0xffffffffu, sum, o);
    if ((t & 31) == 0) sred[t >> 5] = sum;
    __syncthreads();
    if (t < 32) {
        float s2 = (t < 8) ? sred[t] : 0.f;
#pragma unroll
        for (int o = 4; o; o >>= 1) s2 += __shfl_xor_sync(0xffffffffu, s2, o);
        if (t == 0) sred[0] = s2;
    }
    __syncthreads();
    const float inv = 1.0f / sred[0];
    int j = 0;
    for (int i = t; i < MPOS; i += 256) {
        fr[i] = __float2bfloat16(v[j] * inv);
        j++;
    }
    for (int i = MPOS + t; i < MPAD; i += 256) fr[i] = __float2bfloat16(0.f);
}

// ---------------------------------------------------------------------------
// Launch
// ---------------------------------------------------------------------------
extern "C" void kernel_launch(void* const* d_in, const int* in_sizes, int n_in,
                              void* d_out, int out_size) {
    (void)in_sizes; (void)n_in; (void)out_size;
    const float* x     = (const float*)d_in[0];
    const float* g_w   = (const float*)d_in[1];
    const float* g_b   = (const float*)d_in[2];
    const float* th_w  = (const float*)d_in[3];
    const float* th_b  = (const float*)d_in[4];
    const float* ph_w  = (const float*)d_in[5];
    const float* ph_b  = (const float*)d_in[6];
    const float* w_w   = (const float*)d_in[7];
    const float* w_b   = (const float*)d_in[8];
    const float* gamma = (const float*)d_in[9];
    const float* beta  = (const float*)d_in[10];
    float* out = (float*)d_out;

    bf16 *xT, *wbuf, *theta, *scr, *phi, *gmc, *gcm, *fbuf, *ybuf;
    cudaGetSymbolAddress((void**)&xT, d_xT);
    cudaGetSymbolAddress((void**)&wbuf, d_wbuf);
    cudaGetSymbolAddress((void**)&theta, d_theta);
    cudaGetSymbolAddress((void**)&scr, d_scr);
    cudaGetSymbolAddress((void**)&phi, d_phi);
    cudaGetSymbolAddress((void**)&gmc, d_gmc);
    cudaGetSymbolAddress((void**)&gcm, d_gcm);
    cudaGetSymbolAddress((void**)&fbuf, d_fbuf);
    cudaGetSymbolAddress((void**)&ybuf, d_ybuf);

    cudaFuncSetAttribute(mma_nt<1, bf16>, cudaFuncAttributeMaxDynamicSharedMemorySize, SMEM_MMA);
    cudaFuncSetAttribute(mma_nt<0, bf16>, cudaFuncAttributeMaxDynamicSharedMemorySize, SMEM_MMA);
    cudaFuncSetAttribute(mma_nt<2, float>, cudaFuncAttributeMaxDynamicSharedMemorySize, SMEM_MMA);

    bf16* th_wb = wbuf;
    bf16* ph_wb = wbuf + (size_t)CI_DIM * C_DIM;
    bf16* g_wb  = wbuf + (size_t)2 * CI_DIM * C_DIM;
    bf16* w_wb  = wbuf + (size_t)3 * CI_DIM * C_DIM;

    const long sX  = (long)C_DIM * NPOS;
    const long sXT = (long)NPOS * C_DIM;
    const long sTH = (long)NPOS * CI_DIM;
    const long sPH = (long)MPAD * CI_DIM;
    const long sGC = (long)CI_DIM * MPAD;
    const long sF  = (long)NPOS * MPAD;

    const int nw = CI_DIM * C_DIM;
    f2bf_k<<<(nw + 255) / 256, 256>>>(th_w, th_wb, nw);
    f2bf_k<<<(nw + 255) / 256, 256>>>(ph_w, ph_wb, nw);
    f2bf_k<<<(nw + 255) / 256, 256>>>(g_w, g_wb, nw);
    f2bf_k<<<(nw + 255) / 256, 256>>>(w_w, w_wb, nw);

    // 1) x (B,C,N) -> xT bf16 (B,N,C)
    transpose_k<float, bf16><<<dim3(NPOS / 32, C_DIM / 32, BATCH), dim3(32, 8)>>>(
        x, xT, C_DIM, NPOS, C_DIM, sX, sXT);

    const dim3 gConv(CI_DIM / 256, NPOS / 128, BATCH);

    // 2) theta conv
    mma_nt<1, bf16><<<gConv, 256, SMEM_MMA>>>(xT, th_wb, theta, NPOS, CI_DIM, C_DIM,
                                              sXT, 0, sTH, th_b, nullptr, nullptr,
                                              nullptr, nullptr, 0);
    // 3) g conv -> scr, pool -> gmc, transpose -> gcm (Ci,Mpad)
    mma_nt<1, bf16><<<gConv, 256, SMEM_MMA>>>(xT, g_wb, scr, NPOS, CI_DIM, C_DIM,
                                              sXT, 0, sTH, g_b, nullptr, nullptr,
                                              nullptr, nullptr, 0);
    pool_k<<<dim3(CI_DIM / 256, MPOS, BATCH), 256>>>(scr, gmc, MPOS);
    transpose_k<bf16, bf16><<<dim3(CI_DIM / 32, MPOS / 32, BATCH), dim3(32, 8)>>>(
        gmc, gcm, MPOS, CI_DIM, MPAD, (long)MPOS * CI_DIM, sGC);
    // 4) phi conv -> scr, pool -> phi (Mpad,Ci); pad rows stay zero
    mma_nt<1, bf16><<<gConv, 256, SMEM_MMA>>>(xT, ph_wb, scr, NPOS, CI_DIM, C_DIM,
                                              sXT, 0, sTH, ph_b, nullptr, nullptr,
                                              nullptr, nullptr, 0);
    pool_k<<<dim3(CI_DIM / 256, MPOS, BATCH), 256>>>(scr, phi, MPAD);

    // 5) f = theta @ phi^T -> bf16 logits (N,Mpad)
    mma_nt<0, bf16><<<dim3(MPAD / 256, NPOS / 128, BATCH), 256, SMEM_MMA>>>(
        theta, phi, fbuf, NPOS, MPAD, CI_DIM,
        sTH, sPH, sF, nullptr, nullptr, nullptr, nullptr, nullptr, 0);

    // 6) in-place softmax (bf16 logits -> bf16 probs, zeros in pads)
    softmax_rows<<<BATCH * NPOS, 256>>>(fbuf);

    // 7) y = p @ g : (N,Mpad)x(Ci,Mpad)^T -> bf16 (N,Ci)
    mma_nt<0, bf16><<<dim3(CI_DIM / 256, NPOS / 128, BATCH), 256, SMEM_MMA>>>(
        fbuf, gcm, ybuf, NPOS, CI_DIM, MPAD,
        sF, sGC, sTH, nullptr, nullptr, nullptr, nullptr, nullptr, 0);

    // 8) out(C,N) = x + scale*(w_w @ y^T + w_b) + beta
    mma_nt<2, float><<<dim3(NPOS / 256, C_DIM / 128, BATCH), 256, SMEM_MMA>>>(
        w_wb, ybuf, out, C_DIM, NPOS, CI_DIM,
        0, sTH, sX, nullptr, w_b, gamma, beta, x, sX);
}

// round 15
// speedup vs baseline: 1.1522x; 1.1522x over previous
#include <cuda_runtime.h>
#include <cuda_bf16.h>
#include <math.h>
#include <stdint.h>

// ---------------------------------------------------------------------------
// Problem constants
// ---------------------------------------------------------------------------
#define BATCH 4
#define C_DIM 1024
#define CI_DIM 512
#define T_DIM 16
#define H_DIM 28
#define W_DIM 28
#define NPOS (T_DIM * H_DIM * W_DIM)   // 12544
#define TP 8
#define HP 14
#define WP 14
#define MPOS (TP * HP * WP)            // 1568
#define MPAD 1664                      // 13 * 128 (zero-padded attention dim)

typedef __nv_bfloat16 bf16;

// ---------------------------------------------------------------------------
// Scratch (device globals; zero-initialized at load — pad regions never written)
// ---------------------------------------------------------------------------
__device__ bf16  d_xT  [(size_t)BATCH * NPOS * C_DIM];    // x^T  (B,N,C)
__device__ bf16  d_wbuf[(size_t)4 * CI_DIM * C_DIM];      // bf16 weights
__device__ bf16  d_theta[(size_t)BATCH * NPOS * CI_DIM];  // theta (B,N,Ci)
__device__ bf16  d_scr [(size_t)BATCH * NPOS * CI_DIM];   // conv scratch
__device__ bf16  d_phi [(size_t)BATCH * MPAD * CI_DIM];   // phi pooled, M-padded
__device__ bf16  d_gmc [(size_t)BATCH * MPOS * CI_DIM];   // g pooled (B,M,Ci)
__device__ bf16  d_gcm [(size_t)BATCH * CI_DIM * MPAD];   // g pooled^T, M-padded
__device__ bf16  d_fbuf[(size_t)BATCH * NPOS * MPAD];     // logits->probs bf16
__device__ bf16  d_ybuf[(size_t)BATCH * NPOS * CI_DIM];   // y (B,N,Ci)

// ---------------------------------------------------------------------------
// PTX helpers (legacy tensor path — compute_103-safe)
// ---------------------------------------------------------------------------
__device__ __forceinline__ uint32_t smem_u32(const void* p) {
    return (uint32_t)__cvta_generic_to_shared(p);
}
__device__ __forceinline__ void ldmatrix_x4(uint32_t* r, uint32_t addr) {
    asm volatile("ldmatrix.sync.aligned.m8n8.x4.shared.b16 {%0,%1,%2,%3}, [%4];"
                 : "=r"(r[0]), "=r"(r[1]), "=r"(r[2]), "=r"(r[3]) : "r"(addr));
}
__device__ __forceinline__ void mma_16816(float* c, const uint32_t* a, const uint32_t* b) {
    asm volatile("mma.sync.aligned.m16n8k16.row.col.f32.bf16.bf16.f32 "
                 "{%0,%1,%2,%3}, {%4,%5,%6,%7}, {%8,%9}, {%0,%1,%2,%3};"
                 : "+f"(c[0]), "+f"(c[1]), "+f"(c[2]), "+f"(c[3])
                 : "r"(a[0]), "r"(a[1]), "r"(a[2]), "r"(a[3]), "r"(b[0]), "r"(b[1]));
}
__device__ __forceinline__ void cp16(uint32_t s, const void* g) {
    asm volatile("cp.async.cg.shared.global [%0], [%1], 16;" :: "r"(s), "l"(g));
}
#define CP_COMMIT asm volatile("cp.async.commit_group;")
#define CP_WAIT0  asm volatile("cp.async.wait_group 0;")
#define CP_WAIT1  asm volatile("cp.async.wait_group 1;")

// ---------------------------------------------------------------------------
// bf16 NT tensor-core GEMM: C(MxN) = A(MxK) * B(NxK)^T, K-contiguous inputs.
// Tile 128x128, warp tile 64x32 (8 warps), K chunks of 64, 3-stage cp.async
// ring (one __syncthreads per chunk), padded-stride smem (144B rows).
// B fragments via pair-packed ldmatrix.x4 (2 LDSM instead of 4 per k-step).
// Requires M%128==0, N%128==0, K%64==0, K>=128.
// EPI 0: plain   EPI 1: + colBias[col]
// EPI 2: out = resid + gamma[row]/sqrt(1+eps)*(acc + rowBias[row]) + beta[row]
// ---------------------------------------------------------------------------
#define ROWB 144u                 // smem row stride bytes (64*2 + 16 pad)
#define MATB (128u * ROWB)        // 18432 bytes per matrix per stage
#define STGB (2u * MATB)          // 36864 bytes per stage (A + B)
#define SMEM_MMA (3 * (int)STGB)  // 110592 bytes

template <int EPI, typename OutT>
__global__ void __launch_bounds__(256, 2)
mma_nt(const bf16* __restrict__ A, const bf16* __restrict__ B,
       OutT* __restrict__ C, int M, int N, int K,
       long sA, long sB, long sC,
       const float* __restrict__ colBias,
       const float* __restrict__ rowBias,
       const float* __restrict__ gamma,
       const float* __restrict__ beta,
       const float* __restrict__ resid, long sR) {
    extern __shared__ char smem[];
    const uint32_t sbase = smem_u32(smem);
    const int tid = threadIdx.x;
    const int lane = tid & 31;
    const int warp = tid >> 5;
    const int z = blockIdx.z;
    const int m0 = blockIdx.y * 128;
    const int n0 = blockIdx.x * 128;
    const int wm = (warp & 1) * 64;   // warp row offset
    const int wn = (warp >> 1) * 32;  // warp col offset

    const char* gA = (const char*)(A + (long)z * sA) + (long)m0 * K * 2;
    const char* gB = (const char*)(B + (long)z * sB) + (long)n0 * K * 2;
    const long strK = (long)K * 2;
    const int nCh = K >> 6;

    // staging map: chunk = 128 rows x 128B per matrix = 1024 x 16B; 256 thr x 4
    int srow[4];
    uint32_t soff[4];
#pragma unroll
    for (int t = 0; t < 4; t++) {
        const int idx = tid + t * 256;
        srow[t] = idx >> 3;
        soff[t] = (uint32_t)(idx >> 3) * ROWB + (uint32_t)(idx & 7) * 16u;
    }

#define LOAD_CHUNK(buf, ch)                                                   \
    {                                                                         \
        const long cb = (long)(ch) << 7;                                      \
        const uint32_t s0 = sbase + (uint32_t)(buf) * STGB;                   \
        _Pragma("unroll") for (int t = 0; t < 4; t++) {                       \
            const long go = (long)srow[t] * strK + cb + ((soff[t] % ROWB));   \
            cp16(s0 + soff[t], gA + go);                                      \
            cp16(s0 + MATB + soff[t], gB + go);                               \
        }                                                                     \
        CP_COMMIT;                                                            \
    }

    float acc[4][4][4] = {};

    LOAD_CHUNK(0, 0);
    LOAD_CHUNK(1, 1);

    for (int c = 0; c < nCh; ++c) {
        if (c + 1 < nCh) { CP_WAIT1; } else { CP_WAIT0; }
        __syncthreads();
        if (c + 2 < nCh) {
            const int nb = (c + 2) % 3;
            LOAD_CHUNK(nb, c + 2);
        }
        const uint32_t sa = sbase + (uint32_t)(c % 3) * STGB;
        const uint32_t sb = sa + MATB;
#pragma unroll
        for (int ks = 0; ks < 4; ++ks) {
            uint32_t afr[4][4], bfr[4][2];
#pragma unroll
            for (int mi = 0; mi < 4; mi++)
                ldmatrix_x4(afr[mi],
                    sa + (uint32_t)(wm + mi * 16 + (lane & 15)) * ROWB +
                         (uint32_t)ks * 32u + (uint32_t)(lane >> 4) * 16u);
            // B: 32 cols x 16 k = 8 m8n8 matrices = 2 pair-packed ldmatrix.x4
#pragma unroll
            for (int nb = 0; nb < 2; nb++) {
                uint32_t bq[4];
                ldmatrix_x4(bq,
                    sb + (uint32_t)(wn + nb * 16 + (lane & 15)) * ROWB +
                         (uint32_t)ks * 32u + (uint32_t)(lane >> 4) * 16u);
                bfr[2 * nb + 0][0] = bq[0]; bfr[2 * nb + 0][1] = bq[2];
                bfr[2 * nb + 1][0] = bq[1]; bfr[2 * nb + 1][1] = bq[3];
            }
#pragma unroll
            for (int mi = 0; mi < 4; mi++)
#pragma unroll
                for (int ni = 0; ni < 4; ni++)
                    mma_16816(acc[mi][ni], afr[mi], bfr[ni]);
        }
    }

    // ---- epilogue ----
    const int tr = lane >> 2;
    const int tc = (lane & 3) * 2;
    const float bnscale = rsqrtf(1.0f + 1e-5f);
#pragma unroll
    for (int mi = 0; mi < 4; mi++) {
        const int r = m0 + wm + mi * 16 + tr;
#pragma unroll
        for (int ni = 0; ni < 4; ni++) {
            const int c = n0 + wn + ni * 8 + tc;
#pragma unroll
            for (int h = 0; h < 2; h++) {
                const int rr = r + h * 8;
                float v0 = acc[mi][ni][h * 2 + 0];
                float v1 = acc[mi][ni][h * 2 + 1];
                if (EPI == 1) {
                    v0 += colBias[c];
                    v1 += colBias[c + 1];
                } else if (EPI == 2) {
                    const float s = gamma[rr] * bnscale;
                    const float wb = rowBias[rr];
                    const float bt = beta[rr];
                    const float* rp = resid + (long)z * sR + (long)rr * N + c;
                    v0 = rp[0] + s * (v0 + wb) + bt;
                    v1 = rp[1] + s * (v1 + wb) + bt;
                }
                if constexpr (sizeof(OutT) == 2) {
                    __nv_bfloat162 p = __floats2bfloat162_rn(v0, v1);
                    *reinterpret_cast<__nv_bfloat162*>(
                        &((bf16*)(C + (long)z * sC))[(long)rr * N + c]) = p;
                } else {
                    float2 p = make_float2(v0, v1);
                    *reinterpret_cast<float2*>(
                        &((float*)(C + (long)z * sC))[(long)rr * N + c]) = p;
                }
            }
        }
    }
}

// ---------------------------------------------------------------------------
// Tiled transpose with dtype conversion: in (R,Cc) -> out (Cc,R) [ldOut], per z
// ---------------------------------------------------------------------------
__device__ __forceinline__ float ld_as_f(const float* p) { return *p; }
__device__ __forceinline__ float ld_as_f(const bf16* p) { return __bfloat162float(*p); }
__device__ __forceinline__ void st_from_f(float* p, float v) { *p = v; }
__device__ __forceinline__ void st_from_f(bf16* p, float v) { *p = __float2bfloat16(v); }

template <typename TI, typename TO>
__global__ void transpose_k(const TI* __restrict__ in, TO* __restrict__ out,
                            int R, int Cc, int ldOut, long sIn, long sOut) {
    __shared__ float tile[32][33];
    const TI* inb = in + (long)blockIdx.z * sIn;
    TO* outb = out + (long)blockIdx.z * sOut;
    const int c0 = blockIdx.x * 32;
    const int r0 = blockIdx.y * 32;
    const int tx = threadIdx.x, ty = threadIdx.y;
#pragma unroll
    for (int i = 0; i < 32; i += 8)
        tile[ty + i][tx] = ld_as_f(&inb[(long)(r0 + ty + i) * Cc + c0 + tx]);
    __syncthreads();
#pragma unroll
    for (int i = 0; i < 32; i += 8)
        st_from_f(&outb[(long)(c0 + ty + i) * ldOut + r0 + tx], tile[tx][ty + i]);
}

// ---------------------------------------------------------------------------
// fp32 -> bf16 convert for the 4 weight tensors in ONE launch (blockIdx.y picks)
// ---------------------------------------------------------------------------
__global__ void f2bf4_k(const float* __restrict__ w0, const float* __restrict__ w1,
                        const float* __restrict__ w2, const float* __restrict__ w3,
                        bf16* __restrict__ out, int n) {
    const int i = blockIdx.x * 256 + threadIdx.x;
    if (i >= n) return;
    const float* src = (blockIdx.y == 0) ? w0 : (blockIdx.y == 1) ? w1
                     : (blockIdx.y == 2) ? w2 : w3;
    out[(size_t)blockIdx.y * n + i] = __float2bfloat16(src[i]);
}

// ---------------------------------------------------------------------------
// 2x2x2 max pool (bf16): conv (B,NPOS,Ci) -> out (B,outRows,Ci)
// ---------------------------------------------------------------------------
__global__ void pool_k(const bf16* __restrict__ conv, bf16* __restrict__ out,
                       int outRows) {
    const int ci = blockIdx.x * 256 + threadIdx.x;
    const int m = blockIdx.y;
    const int b = blockIdx.z;
    const int wp = m % WP;
    const int hp = (m / WP) % HP;
    const int tp = m / (WP * HP);
    const bf16* cb = conv + (long)b * NPOS * CI_DIM;
    const long n0 = (long)(2 * tp) * (H_DIM * W_DIM) + (long)(2 * hp) * W_DIM + 2 * wp;
    float mx = -INFINITY;
#pragma unroll
    for (int dt = 0; dt < 2; dt++)
#pragma unroll
        for (int dh = 0; dh < 2; dh++)
#pragma unroll
            for (int dw = 0; dw < 2; dw++) {
                long n = n0 + dt * (H_DIM * W_DIM) + dh * W_DIM + dw;
                mx = fmaxf(mx, __bfloat162float(cb[n * CI_DIM + ci]));
            }
    out[((long)b * outRows + m) * CI_DIM + ci] = __float2bfloat16(mx);
}

// ---------------------------------------------------------------------------
// In-place row softmax on bf16 logits (stride MPAD, MPOS valid); zeros the pads.
// ---------------------------------------------------------------------------
__global__ void __launch_bounds__(256) softmax_rows(bf16* __restrict__ f) {
    bf16* fr = f + (long)blockIdx.x * MPAD;
    const int t = threadIdx.x;
    float v[7];
    int cnt = 0;
    float mx = -1e30f;
    for (int i = t; i < MPOS; i += 256) {
        v[cnt] = __bfloat162float(fr[i]);
        mx = fmaxf(mx, v[cnt]);
        cnt++;
    }
    __shared__ float sred[8];
#pragma unroll
    for (int o = 16; o; o >>= 1) mx = fmaxf(mx, __shfl_xor_sync(0xffffffffu, mx, o));
    if ((t & 31) == 0) sred[t >> 5] = mx;
    __syncthreads();
    if (t < 32) {
        float m2 = (t < 8) ? sred[t] : -1e30f;
#pragma unroll
        for (int o = 4; o; o >>= 1) m2 = fmaxf(m2, __shfl_xor_sync(0xffffffffu, m2, o));
        if (t == 0) sred[0] = m2;
    }
    __syncthreads();
    mx = sred[0];
    float sum = 0.f;
    for (int j = 0; j < cnt; j++) {
        v[j] = __expf(v[j] - mx);
        sum += v[j];
    }
    __syncthreads();
#pragma unroll
    for (int o = 16; o; o >>= 1) sum += __shfl_xor_sync(0xffffffffu, sum, o);
    if ((t & 31) == 0) sred[t >> 5] = sum;
    __syncthreads();
    if (t < 32) {
        float s2 = (t < 8) ? sred[t] : 0.f;
#pragma unroll
        for (int o = 4; o; o >>= 1) s2 += __shfl_xor_sync(0xffffffffu, s2, o);
        if (t == 0) sred[0] = s2;
    }
    __syncthreads();
    const float inv = 1.0f / sred[0];
    int j = 0;
    for (int i = t; i < MPOS; i += 256) {
        fr[i] = __float2bfloat16(v[j] * inv);
        j++;
    }
    for (int i = MPOS + t; i < MPAD; i += 256) fr[i] = __float2bfloat16(0.f);
}

// ---------------------------------------------------------------------------
// Launch
// ---------------------------------------------------------------------------
extern "C" void kernel_launch(void* const* d_in, const int* in_sizes, int n_in,
                              void* d_out, int out_size) {
    (void)in_sizes; (void)n_in; (void)out_size;
    const float* x     = (const float*)d_in[0];
    const float* g_w   = (const float*)d_in[1];
    const float* g_b   = (const float*)d_in[2];
    const float* th_w  = (const float*)d_in[3];
    const float* th_b  = (const float*)d_in[4];
    const float* ph_w  = (const float*)d_in[5];
    const float* ph_b  = (const float*)d_in[6];
    const float* w_w   = (const float*)d_in[7];
    const float* w_b   = (const float*)d_in[8];
    const float* gamma = (const float*)d_in[9];
    const float* beta  = (const float*)d_in[10];
    float* out = (float*)d_out;

    bf16 *xT, *wbuf, *theta, *scr, *phi, *gmc, *gcm, *fbuf, *ybuf;
    cudaGetSymbolAddress((void**)&xT, d_xT);
    cudaGetSymbolAddress((void**)&wbuf, d_wbuf);
    cudaGetSymbolAddress((void**)&theta, d_theta);
    cudaGetSymbolAddress((void**)&scr, d_scr);
    cudaGetSymbolAddress((void**)&phi, d_phi);
    cudaGetSymbolAddress((void**)&gmc, d_gmc);
    cudaGetSymbolAddress((void**)&gcm, d_gcm);
    cudaGetSymbolAddress((void**)&fbuf, d_fbuf);
    cudaGetSymbolAddress((void**)&ybuf, d_ybuf);

    cudaFuncSetAttribute(mma_nt<1, bf16>, cudaFuncAttributeMaxDynamicSharedMemorySize, SMEM_MMA);
    cudaFuncSetAttribute(mma_nt<0, bf16>, cudaFuncAttributeMaxDynamicSharedMemorySize, SMEM_MMA);
    cudaFuncSetAttribute(mma_nt<2, float>, cudaFuncAttributeMaxDynamicSharedMemorySize, SMEM_MMA);

    bf16* th_wb = wbuf;
    bf16* ph_wb = wbuf + (size_t)CI_DIM * C_DIM;
    bf16* g_wb  = wbuf + (size_t)2 * CI_DIM * C_DIM;
    bf16* w_wb  = wbuf + (size_t)3 * CI_DIM * C_DIM;

    const long sX  = (long)C_DIM * NPOS;
    const long sXT = (long)NPOS * C_DIM;
    const long sTH = (long)NPOS * CI_DIM;
    const long sPH = (long)MPAD * CI_DIM;
    const long sGC = (long)CI_DIM * MPAD;
    const long sF  = (long)NPOS * MPAD;

    const int nw = CI_DIM * C_DIM;
    // weights -> bf16, one launch (order in wbuf: th, ph, g, w)
    f2bf4_k<<<dim3((nw + 255) / 256, 4), 256>>>(th_w, ph_w, g_w, w_w, wbuf, nw);

    // 1) x (B,C,N) -> xT bf16 (B,N,C)
    transpose_k<float, bf16><<<dim3(NPOS / 32, C_DIM / 32, BATCH), dim3(32, 8)>>>(
        x, xT, C_DIM, NPOS, C_DIM, sX, sXT);

    const dim3 gConv(CI_DIM / 128, NPOS / 128, BATCH);

    // 2) theta conv
    mma_nt<1, bf16><<<gConv, 256, SMEM_MMA>>>(xT, th_wb, theta, NPOS, CI_DIM, C_DIM,
                                              sXT, 0, sTH, th_b, nullptr, nullptr,
                                              nullptr, nullptr, 0);
    // 3) g conv -> scr, pool -> gmc, transpose -> gcm (Ci,Mpad)
    mma_nt<1, bf16><<<gConv, 256, SMEM_MMA>>>(xT, g_wb, scr, NPOS, CI_DIM, C_DIM,
                                              sXT, 0, sTH, g_b, nullptr, nullptr,
                                              nullptr, nullptr, 0);
    pool_k<<<dim3(CI_DIM / 256, MPOS, BATCH), 256>>>(scr, gmc, MPOS);
    transpose_k<bf16, bf16><<<dim3(CI_DIM / 32, MPOS / 32, BATCH), dim3(32, 8)>>>(
        gmc, gcm, MPOS, CI_DIM, MPAD, (long)MPOS * CI_DIM, sGC);
    // 4) phi conv -> scr, pool -> phi (Mpad,Ci); pad rows stay zero
    mma_nt<1, bf16><<<gConv, 256, SMEM_MMA>>>(xT, ph_wb, scr, NPOS, CI_DIM, C_DIM,
                                              sXT, 0, sTH, ph_b, nullptr, nullptr,
                                              nullptr, nullptr, 0);
    pool_k<<<dim3(CI_DIM / 256, MPOS, BATCH), 256>>>(scr, phi, MPAD);

    // 5) f = theta @ phi^T -> bf16 logits (N,Mpad)
    mma_nt<0, bf16><<<dim3(MPAD / 128, NPOS / 128, BATCH), 256, SMEM_MMA>>>(
        theta, phi, fbuf, NPOS, MPAD, CI_DIM,
        sTH, sPH, sF, nullptr, nullptr, nullptr, nullptr, nullptr, 0);

    // 6) in-place softmax (bf16 logits -> bf16 probs, zeros in pads)
    softmax_rows<<<BATCH * NPOS, 256>>>(fbuf);

    // 7) y = p @ g : (N,Mpad)x(Ci,Mpad)^T -> bf16 (N,Ci)
    mma_nt<0, bf16><<<dim3(CI_DIM / 128, NPOS / 128, BATCH), 256, SMEM_MMA>>>(
        fbuf, gcm, ybuf, NPOS, CI_DIM, MPAD,
        sF, sGC, sTH, nullptr, nullptr, nullptr, nullptr, nullptr, 0);

    // 8) out(C,N) = x + scale*(w_w @ y^T + w_b) + beta
    mma_nt<2, float><<<dim3(NPOS / 128, C_DIM / 128, BATCH), 256, SMEM_MMA>>>(
        w_wb, ybuf, out, C_DIM, NPOS, CI_DIM,
        0, sTH, sX, nullptr, w_b, gamma, beta, x, sX);
}

// round 16
// speedup vs baseline: 1.2836x; 1.1140x over previous
#include <cuda_runtime.h>
#include <cuda_bf16.h>
#include <math.h>
#include <stdint.h>

// ---------------------------------------------------------------------------
// Problem constants
// ---------------------------------------------------------------------------
#define BATCH 4
#define C_DIM 1024
#define CI_DIM 512
#define T_DIM 16
#define H_DIM 28
#define W_DIM 28
#define NPOS (T_DIM * H_DIM * W_DIM)   // 12544
#define TP 8
#define HP 14
#define WP 14
#define MPOS (TP * HP * WP)            // 1568
#define MPAD 1664                      // 13 * 128 (zero-padded attention dim)
#define C3 (3 * CI_DIM)                // 1536 fused conv output width

typedef __nv_bfloat16 bf16;

// ---------------------------------------------------------------------------
// Scratch (device globals; zero-initialized at load — pad regions never written)
// ---------------------------------------------------------------------------
__device__ bf16  d_xT  [(size_t)BATCH * NPOS * C_DIM];    // x^T  (B,N,C)
__device__ bf16  d_wbuf[(size_t)4 * CI_DIM * C_DIM];      // bf16 weights th,ph,g,w
__device__ float d_cbias[C3];                             // concat th_b|ph_b|g_b
__device__ bf16  d_scr2[(size_t)BATCH * NPOS * C3];       // fused conv out (N,1536)
__device__ bf16  d_phi [(size_t)BATCH * MPAD * CI_DIM];   // phi pooled, M-padded
__device__ bf16  d_gmc [(size_t)BATCH * MPOS * CI_DIM];   // g pooled (B,M,Ci)
__device__ bf16  d_gcm [(size_t)BATCH * CI_DIM * MPAD];   // g pooled^T, M-padded
__device__ bf16  d_fbuf[(size_t)BATCH * NPOS * MPAD];     // logits->probs bf16
__device__ bf16  d_ybuf[(size_t)BATCH * NPOS * CI_DIM];   // y (B,N,Ci)

// ---------------------------------------------------------------------------
// PTX helpers (legacy tensor path — compute_103-safe)
// ---------------------------------------------------------------------------
__device__ __forceinline__ uint32_t smem_u32(const void* p) {
    return (uint32_t)__cvta_generic_to_shared(p);
}
__device__ __forceinline__ void ldmatrix_x4(uint32_t* r, uint32_t addr) {
    asm volatile("ldmatrix.sync.aligned.m8n8.x4.shared.b16 {%0,%1,%2,%3}, [%4];"
                 : "=r"(r[0]), "=r"(r[1]), "=r"(r[2]), "=r"(r[3]) : "r"(addr));
}
__device__ __forceinline__ void ldmatrix_x2(uint32_t* r, uint32_t addr) {
    asm volatile("ldmatrix.sync.aligned.m8n8.x2.shared.b16 {%0,%1}, [%2];"
                 : "=r"(r[0]), "=r"(r[1]) : "r"(addr));
}
__device__ __forceinline__ void mma_16816(float* c, const uint32_t* a, const uint32_t* b) {
    asm volatile("mma.sync.aligned.m16n8k16.row.col.f32.bf16.bf16.f32 "
                 "{%0,%1,%2,%3}, {%4,%5,%6,%7}, {%8,%9}, {%0,%1,%2,%3};"
                 : "+f"(c[0]), "+f"(c[1]), "+f"(c[2]), "+f"(c[3])
                 : "r"(a[0]), "r"(a[1]), "r"(a[2]), "r"(a[3]), "r"(b[0]), "r"(b[1]));
}
__device__ __forceinline__ void cp16(uint32_t s, const void* g) {
    asm volatile("cp.async.cg.shared.global [%0], [%1], 16;" :: "r"(s), "l"(g));
}
#define CP_COMMIT asm volatile("cp.async.commit_group;")
#define CP_WAIT0  asm volatile("cp.async.wait_group 0;")
#define CP_WAIT1  asm volatile("cp.async.wait_group 1;")

// ---------------------------------------------------------------------------
// bf16 NT tensor-core GEMM: C(MxN) = A(MxK) * B(NxK)^T, K-contiguous inputs
// with leading dims lda/ldb (elements) and output leading dim ldc.
// Tile 128x128, warp tile 64x32 (8 warps), K chunks of 64, 3-stage cp.async
// ring (one __syncthreads per chunk), padded-stride smem (144B rows).
// Requires M%128==0, N%128==0, K%64==0, K>=128.
// EPI 0: plain   EPI 1: + colBias[col]
// EPI 2: out = resid + gamma[row]/sqrt(1+eps)*(acc + rowBias[row]) + beta[row]
// ---------------------------------------------------------------------------
#define ROWB 144u                 // smem row stride bytes (64*2 + 16 pad)
#define MATB (128u * ROWB)        // 18432 bytes per matrix per stage
#define STGB (2u * MATB)          // 36864 bytes per stage (A + B)
#define SMEM_MMA (3 * (int)STGB)  // 110592 bytes

template <int EPI, typename OutT>
__global__ void __launch_bounds__(256, 2)
mma_nt(const bf16* __restrict__ A, const bf16* __restrict__ B,
       OutT* __restrict__ C, int K, int lda, int ldb, int ldc,
       long sA, long sB, long sC,
       const float* __restrict__ colBias,
       const float* __restrict__ rowBias,
       const float* __restrict__ gamma,
       const float* __restrict__ beta,
       const float* __restrict__ resid, long sR) {
    extern __shared__ char smem[];
    const uint32_t sbase = smem_u32(smem);
    const int tid = threadIdx.x;
    const int lane = tid & 31;
    const int warp = tid >> 5;
    const int z = blockIdx.z;
    const int m0 = blockIdx.y * 128;
    const int n0 = blockIdx.x * 128;
    const int wm = (warp & 1) * 64;   // warp row offset
    const int wn = (warp >> 1) * 32;  // warp col offset

    const char* gA = (const char*)(A + (long)z * sA) + (long)m0 * lda * 2;
    const char* gB = (const char*)(B + (long)z * sB) + (long)n0 * ldb * 2;
    const long strA = (long)lda * 2;
    const long strB = (long)ldb * 2;
    const int nCh = K >> 6;

    // staging map: chunk = 128 rows x 128B per matrix = 1024 x 16B; 256 thr x 4
    int srow[4];
    uint32_t soff[4];
#pragma unroll
    for (int t = 0; t < 4; t++) {
        const int idx = tid + t * 256;
        srow[t] = idx >> 3;
        soff[t] = (uint32_t)(idx >> 3) * ROWB + (uint32_t)(idx & 7) * 16u;
    }

#define LOAD_CHUNK(buf, ch)                                                   \
    {                                                                         \
        const long cb = (long)(ch) << 7;                                      \
        const uint32_t s0 = sbase + (uint32_t)(buf) * STGB;                   \
        _Pragma("unroll") for (int t = 0; t < 4; t++) {                       \
            const long ko = cb + (soff[t] % ROWB);                            \
            cp16(s0 + soff[t], gA + (long)srow[t] * strA + ko);               \
            cp16(s0 + MATB + soff[t], gB + (long)srow[t] * strB + ko);        \
        }                                                                     \
        CP_COMMIT;                                                            \
    }

    float acc[4][4][4] = {};

    LOAD_CHUNK(0, 0);
    LOAD_CHUNK(1, 1);

    for (int c = 0; c < nCh; ++c) {
        if (c + 1 < nCh) { CP_WAIT1; } else { CP_WAIT0; }
        __syncthreads();
        if (c + 2 < nCh) {
            const int nb = (c + 2) % 3;
            LOAD_CHUNK(nb, c + 2);
        }
        const uint32_t sa = sbase + (uint32_t)(c % 3) * STGB;
        const uint32_t sb = sa + MATB;
#pragma unroll
        for (int ks = 0; ks < 4; ++ks) {
            uint32_t afr[4][4], bfr[4][2];
#pragma unroll
            for (int mi = 0; mi < 4; mi++)
                ldmatrix_x4(afr[mi],
                    sa + (uint32_t)(wm + mi * 16 + (lane & 15)) * ROWB +
                         (uint32_t)ks * 32u + (uint32_t)(lane >> 4) * 16u);
#pragma unroll
            for (int ni = 0; ni < 4; ni++)
                ldmatrix_x2(bfr[ni],
                    sb + (uint32_t)(wn + ni * 8 + (lane & 7)) * ROWB +
                         (uint32_t)ks * 32u + (uint32_t)((lane >> 3) & 1) * 16u);
#pragma unroll
            for (int mi = 0; mi < 4; mi++)
#pragma unroll
                for (int ni = 0; ni < 4; ni++)
                    mma_16816(acc[mi][ni], afr[mi], bfr[ni]);
        }
    }

    // ---- epilogue ----
    const int tr = lane >> 2;
    const int tc = (lane & 3) * 2;
    const float bnscale = rsqrtf(1.0f + 1e-5f);
#pragma unroll
    for (int mi = 0; mi < 4; mi++) {
        const int r = m0 + wm + mi * 16 + tr;
#pragma unroll
        for (int ni = 0; ni < 4; ni++) {
            const int c = n0 + wn + ni * 8 + tc;
#pragma unroll
            for (int h = 0; h < 2; h++) {
                const int rr = r + h * 8;
                float v0 = acc[mi][ni][h * 2 + 0];
                float v1 = acc[mi][ni][h * 2 + 1];
                if (EPI == 1) {
                    v0 += colBias[c];
                    v1 += colBias[c + 1];
                } else if (EPI == 2) {
                    const float s = gamma[rr] * bnscale;
                    const float wb = rowBias[rr];
                    const float bt = beta[rr];
                    const float* rp = resid + (long)z * sR + (long)rr * ldc + c;
                    v0 = rp[0] + s * (v0 + wb) + bt;
                    v1 = rp[1] + s * (v1 + wb) + bt;
                }
                if constexpr (sizeof(OutT) == 2) {
                    __nv_bfloat162 p = __floats2bfloat162_rn(v0, v1);
                    *reinterpret_cast<__nv_bfloat162*>(
                        &((bf16*)(C + (long)z * sC))[(long)rr * ldc + c]) = p;
                } else {
                    float2 p = make_float2(v0, v1);
                    *reinterpret_cast<float2*>(
                        &((float*)(C + (long)z * sC))[(long)rr * ldc + c]) = p;
                }
            }
        }
    }
}

// ---------------------------------------------------------------------------
// Tiled transpose with dtype conversion: in (R,Cc) -> out (Cc,R) [ldOut], per z
// ---------------------------------------------------------------------------
__device__ __forceinline__ float ld_as_f(const float* p) { return *p; }
__device__ __forceinline__ float ld_as_f(const bf16* p) { return __bfloat162float(*p); }
__device__ __forceinline__ void st_from_f(float* p, float v) { *p = v; }
__device__ __forceinline__ void st_from_f(bf16* p, float v) { *p = __float2bfloat16(v); }

template <typename TI, typename TO>
__global__ void transpose_k(const TI* __restrict__ in, TO* __restrict__ out,
                            int R, int Cc, int ldOut, long sIn, long sOut) {
    __shared__ float tile[32][33];
    const TI* inb = in + (long)blockIdx.z * sIn;
    TO* outb = out + (long)blockIdx.z * sOut;
    const int c0 = blockIdx.x * 32;
    const int r0 = blockIdx.y * 32;
    const int tx = threadIdx.x, ty = threadIdx.y;
#pragma unroll
    for (int i = 0; i < 32; i += 8)
        tile[ty + i][tx] = ld_as_f(&inb[(long)(r0 + ty + i) * Cc + c0 + tx]);
    __syncthreads();
#pragma unroll
    for (int i = 0; i < 32; i += 8)
        st_from_f(&outb[(long)(c0 + ty + i) * ldOut + r0 + tx], tile[tx][ty + i]);
}

// ---------------------------------------------------------------------------
// fp32 -> bf16 convert for the 4 weight tensors in ONE launch (blockIdx.y picks)
// ---------------------------------------------------------------------------
__global__ void f2bf4_k(const float* __restrict__ w0, const float* __restrict__ w1,
                        const float* __restrict__ w2, const float* __restrict__ w3,
                        bf16* __restrict__ out, int n) {
    const int i = blockIdx.x * 256 + threadIdx.x;
    if (i >= n) return;
    const float* src = (blockIdx.y == 0) ? w0 : (blockIdx.y == 1) ? w1
                     : (blockIdx.y == 2) ? w2 : w3;
    out[(size_t)blockIdx.y * n + i] = __float2bfloat16(src[i]);
}

// concat th_b | ph_b | g_b into d_cbias (each CI_DIM long)
__global__ void catbias_k(const float* __restrict__ b0, const float* __restrict__ b1,
                          const float* __restrict__ b2, float* __restrict__ out) {
    const int i = blockIdx.x * 256 + threadIdx.x;
    if (i < CI_DIM) out[i] = b0[i];
    else if (i < 2 * CI_DIM) out[i] = b1[i - CI_DIM];
    else if (i < C3) out[i] = b2[i - 2 * CI_DIM];
}

// ---------------------------------------------------------------------------
// 2x2x2 max pool (bf16): in (B,NPOS,ldIn) at column offset cb ->
// out (B,outRows,CI_DIM)
// ---------------------------------------------------------------------------
__global__ void pool_k(const bf16* __restrict__ conv, bf16* __restrict__ out,
                       int outRows, int ldIn, int cb) {
    const int ci = blockIdx.x * 256 + threadIdx.x;
    const int m = blockIdx.y;
    const int b = blockIdx.z;
    const int wp = m % WP;
    const int hp = (m / WP) % HP;
    const int tp = m / (WP * HP);
    const bf16* cbp = conv + (long)b * NPOS * ldIn + cb;
    const long n0 = (long)(2 * tp) * (H_DIM * W_DIM) + (long)(2 * hp) * W_DIM + 2 * wp;
    float mx = -INFINITY;
#pragma unroll
    for (int dt = 0; dt < 2; dt++)
#pragma unroll
        for (int dh = 0; dh < 2; dh++)
#pragma unroll
            for (int dw = 0; dw < 2; dw++) {
                long n = n0 + dt * (H_DIM * W_DIM) + dh * W_DIM + dw;
                mx = fmaxf(mx, __bfloat162float(cbp[n * ldIn + ci]));
            }
    out[((long)b * outRows + m) * CI_DIM + ci] = __float2bfloat16(mx);
}

// ---------------------------------------------------------------------------
// In-place row softmax on bf16 logits (stride MPAD, MPOS valid); zeros the pads.
// ---------------------------------------------------------------------------
__global__ void __launch_bounds__(256) softmax_rows(bf16* __restrict__ f) {
    bf16* fr = f + (long)blockIdx.x * MPAD;
    const int t = threadIdx.x;
    float v[7];
    int cnt = 0;
    float mx = -1e30f;
    for (int i = t; i < MPOS; i += 256) {
        v[cnt] = __bfloat162float(fr[i]);
        mx = fmaxf(mx, v[cnt]);
        cnt++;
    }
    __shared__ float sred[8];
#pragma unroll
    for (int o = 16; o; o >>= 1) mx = fmaxf(mx, __shfl_xor_sync(0xffffffffu, mx, o));
    if ((t & 31) == 0) sred[t >> 5] = mx;
    __syncthreads();
    if (t < 32) {
        float m2 = (t < 8) ? sred[t] : -1e30f;
#pragma unroll
        for (int o = 4; o; o >>= 1) m2 = fmaxf(m2, __shfl_xor_sync(0xffffffffu, m2, o));
        if (t == 0) sred[0] = m2;
    }
    __syncthreads();
    mx = sred[0];
    float sum = 0.f;
    for (int j = 0; j < cnt; j++) {
        v[j] = __expf(v[j] - mx);
        sum += v[j];
    }
    __syncthreads();
#pragma unroll
    for (int o = 16; o; o >>= 1) sum += __shfl_xor_sync(0xffffffffu, sum, o);
    if ((t & 31) == 0) sred[t >> 5] = sum;
    __syncthreads();
    if (t < 32) {
        float s2 = (t < 8) ? sred[t] : 0.f;
#pragma unroll
        for (int o = 4; o; o >>= 1) s2 += __shfl_xor_sync(0xffffffffu, s2, o);
        if (t == 0) sred[0] = s2;
    }
    __syncthreads();
    const float inv = 1.0f / sred[0];
    int j = 0;
    for (int i = t; i < MPOS; i += 256) {
        fr[i] = __float2bfloat16(v[j] * inv);
        j++;
    }
    for (int i = MPOS + t; i < MPAD; i += 256) fr[i] = __float2bfloat16(0.f);
}

// ---------------------------------------------------------------------------
// Launch
// ---------------------------------------------------------------------------
extern "C" void kernel_launch(void* const* d_in, const int* in_sizes, int n_in,
                              void* d_out, int out_size) {
    (void)in_sizes; (void)n_in; (void)out_size;
    const float* x     = (const float*)d_in[0];
    const float* g_w   = (const float*)d_in[1];
    const float* g_b   = (const float*)d_in[2];
    const float* th_w  = (const float*)d_in[3];
    const float* th_b  = (const float*)d_in[4];
    const float* ph_w  = (const float*)d_in[5];
    const float* ph_b  = (const float*)d_in[6];
    const float* w_w   = (const float*)d_in[7];
    const float* w_b   = (const float*)d_in[8];
    const float* gamma = (const float*)d_in[9];
    const float* beta  = (const float*)d_in[10];
    float* out = (float*)d_out;

    bf16 *xT, *wbuf, *scr2, *phi, *gmc, *gcm, *fbuf, *ybuf;
    float* cbias;
    cudaGetSymbolAddress((void**)&xT, d_xT);
    cudaGetSymbolAddress((void**)&wbuf, d_wbuf);
    cudaGetSymbolAddress((void**)&cbias, d_cbias);
    cudaGetSymbolAddress((void**)&scr2, d_scr2);
    cudaGetSymbolAddress((void**)&phi, d_phi);
    cudaGetSymbolAddress((void**)&gmc, d_gmc);
    cudaGetSymbolAddress((void**)&gcm, d_gcm);
    cudaGetSymbolAddress((void**)&fbuf, d_fbuf);
    cudaGetSymbolAddress((void**)&ybuf, d_ybuf);

    cudaFuncSetAttribute(mma_nt<1, bf16>, cudaFuncAttributeMaxDynamicSharedMemorySize, SMEM_MMA);
    cudaFuncSetAttribute(mma_nt<0, bf16>, cudaFuncAttributeMaxDynamicSharedMemorySize, SMEM_MMA);
    cudaFuncSetAttribute(mma_nt<2, float>, cudaFuncAttributeMaxDynamicSharedMemorySize, SMEM_MMA);

    bf16* w_wb = wbuf + (size_t)3 * CI_DIM * C_DIM;  // (C, Ci)

    const long sX  = (long)C_DIM * NPOS;             // x batch stride
    const long sXT = (long)NPOS * C_DIM;
    const long sS2 = (long)NPOS * C3;
    const long sY  = (long)NPOS * CI_DIM;
    const long sPH = (long)MPAD * CI_DIM;
    const long sGC = (long)CI_DIM * MPAD;
    const long sF  = (long)NPOS * MPAD;

    const int nw = CI_DIM * C_DIM;
    // weights -> bf16: wbuf = [th | ph | g | w]; rows 0..1535 form fused conv W
    f2bf4_k<<<dim3((nw + 255) / 256, 4), 256>>>(th_w, ph_w, g_w, w_w, wbuf, nw);
    catbias_k<<<(C3 + 255) / 256, 256>>>(th_b, ph_b, g_b, cbias);

    // 1) x (B,C,N) -> xT bf16 (B,N,C)
    transpose_k<float, bf16><<<dim3(NPOS / 32, C_DIM / 32, BATCH), dim3(32, 8)>>>(
        x, xT, C_DIM, NPOS, C_DIM, sX, sXT);

    // 2) fused conv: scr2(N,1536) = xT @ [th|ph|g]^T + cbias
    mma_nt<1, bf16><<<dim3(C3 / 128, NPOS / 128, BATCH), 256, SMEM_MMA>>>(
        xT, wbuf, scr2, C_DIM, C_DIM, C_DIM, C3,
        sXT, 0, sS2, cbias, nullptr, nullptr, nullptr, nullptr, 0);

    // 3) pools: g cols [1024..1536) -> gmc; phi cols [512..1024) -> phi (Mpad)
    pool_k<<<dim3(CI_DIM / 256, MPOS, BATCH), 256>>>(scr2, gmc, MPOS, C3, 2 * CI_DIM);
    transpose_k<bf16, bf16><<<dim3(CI_DIM / 32, MPOS / 32, BATCH), dim3(32, 8)>>>(
        gmc, gcm, MPOS, CI_DIM, MPAD, (long)MPOS * CI_DIM, sGC);
    pool_k<<<dim3(CI_DIM / 256, MPOS, BATCH), 256>>>(scr2, phi, MPAD, C3, CI_DIM);

    // 4) f = theta @ phi^T -> bf16 logits (N,Mpad); theta = scr2 cols [0,512)
    mma_nt<0, bf16><<<dim3(MPAD / 128, NPOS / 128, BATCH), 256, SMEM_MMA>>>(
        scr2, phi, fbuf, CI_DIM, C3, CI_DIM, MPAD,
        sS2, sPH, sF, nullptr, nullptr, nullptr, nullptr, nullptr, 0);

    // 5) in-place softmax (bf16 logits -> bf16 probs, zeros in pads)
    softmax_rows<<<BATCH * NPOS, 256>>>(fbuf);

    // 6) y = p @ g : (N,Mpad)x(Ci,Mpad)^T -> bf16 (N,Ci)
    mma_nt<0, bf16><<<dim3(CI_DIM / 128, NPOS / 128, BATCH), 256, SMEM_MMA>>>(
        fbuf, gcm, ybuf, MPAD, MPAD, MPAD, CI_DIM,
        sF, sGC, sY, nullptr, nullptr, nullptr, nullptr, nullptr, 0);

    // 7) out(C,N) = x + scale*(w_w @ y^T + w_b) + beta
    mma_nt<2, float><<<dim3(NPOS / 128, C_DIM / 128, BATCH), 256, SMEM_MMA>>>(
        w_wb, ybuf, out, CI_DIM, CI_DIM, CI_DIM, NPOS,
        0, sY, sX, nullptr, w_b, gamma, beta, x, sX);
}

// round 17
// speedup vs baseline: 1.3503x; 1.0520x over previous
#include <cuda_runtime.h>
#include <cuda_bf16.h>
#include <math.h>
#include <stdint.h>

// ---------------------------------------------------------------------------
// Problem constants
// ---------------------------------------------------------------------------
#define BATCH 4
#define C_DIM 1024
#define CI_DIM 512
#define T_DIM 16
#define H_DIM 28
#define W_DIM 28
#define NPOS (T_DIM * H_DIM * W_DIM)   // 12544
#define TP 8
#define HP 14
#define WP 14
#define MPOS (TP * HP * WP)            // 1568
#define MPAD 1664                      // 13 * 128 (zero-padded attention dim)
#define C3 (3 * CI_DIM)                // 1536 fused conv output width

typedef __nv_bfloat16 bf16;

// ---------------------------------------------------------------------------
// Scratch (device globals; zero-initialized at load — pad regions never written)
// ---------------------------------------------------------------------------
__device__ bf16  d_xT  [(size_t)BATCH * NPOS * C_DIM];    // x^T  (B,N,C)
__device__ bf16  d_wbuf[(size_t)4 * CI_DIM * C_DIM];      // bf16 weights th,ph,g,w
__device__ float d_cbias[C3];                             // concat th_b|ph_b|g_b
__device__ bf16  d_scr2[(size_t)BATCH * NPOS * C3];       // fused conv out (N,1536)
__device__ bf16  d_phi [(size_t)BATCH * MPAD * CI_DIM];   // phi pooled, M-padded
__device__ bf16  d_gmc [(size_t)BATCH * MPOS * CI_DIM];   // g pooled (B,M,Ci)
__device__ bf16  d_gcm [(size_t)BATCH * CI_DIM * MPAD];   // g pooled^T, M-padded
__device__ bf16  d_fbuf[(size_t)BATCH * NPOS * MPAD];     // logits->probs bf16
__device__ bf16  d_ybuf[(size_t)BATCH * NPOS * CI_DIM];   // y (B,N,Ci)

// ---------------------------------------------------------------------------
// PTX helpers (legacy tensor path — compute_103-safe)
// ---------------------------------------------------------------------------
__device__ __forceinline__ uint32_t smem_u32(const void* p) {
    return (uint32_t)__cvta_generic_to_shared(p);
}
__device__ __forceinline__ void ldmatrix_x4(uint32_t* r, uint32_t addr) {
    asm volatile("ldmatrix.sync.aligned.m8n8.x4.shared.b16 {%0,%1,%2,%3}, [%4];"
                 : "=r"(r[0]), "=r"(r[1]), "=r"(r[2]), "=r"(r[3]) : "r"(addr));
}
__device__ __forceinline__ void ldmatrix_x2(uint32_t* r, uint32_t addr) {
    asm volatile("ldmatrix.sync.aligned.m8n8.x2.shared.b16 {%0,%1}, [%2];"
                 : "=r"(r[0]), "=r"(r[1]) : "r"(addr));
}
__device__ __forceinline__ void mma_16816(float* c, const uint32_t* a, const uint32_t* b) {
    asm volatile("mma.sync.aligned.m16n8k16.row.col.f32.bf16.bf16.f32 "
                 "{%0,%1,%2,%3}, {%4,%5,%6,%7}, {%8,%9}, {%0,%1,%2,%3};"
                 : "+f"(c[0]), "+f"(c[1]), "+f"(c[2]), "+f"(c[3])
                 : "r"(a[0]), "r"(a[1]), "r"(a[2]), "r"(a[3]), "r"(b[0]), "r"(b[1]));
}
__device__ __forceinline__ void cp16(uint32_t s, const void* g) {
    asm volatile("cp.async.cg.shared.global [%0], [%1], 16;" :: "r"(s), "l"(g));
}
#define CP_COMMIT asm volatile("cp.async.commit_group;")
#define CP_WAIT0  asm volatile("cp.async.wait_group 0;")
#define CP_WAIT1  asm volatile("cp.async.wait_group 1;")

// ---------------------------------------------------------------------------
// bf16 NT tensor-core GEMM: C(MxN) = A(MxK) * B(NxK)^T, K-contiguous inputs.
// Compile-time K / leading dims. Tile 128x128, warp tile 64x32 (8 warps),
// K chunks of 64, 3-stage cp.async ring (one __syncthreads per chunk),
// padded-stride smem (144B rows). B fragments double-buffered across k-steps.
// Requires M%128==0, N%128==0, K%64==0, K>=128.
// EPI 0: plain   EPI 1: + colBias[col]
// EPI 2: out = resid + gamma[row]/sqrt(1+eps)*(acc + rowBias[row]) + beta[row]
// ---------------------------------------------------------------------------
#define ROWB 144u                 // smem row stride bytes (64*2 + 16 pad)
#define MATB (128u * ROWB)        // 18432 bytes per matrix per stage
#define STGB (2u * MATB)          // 36864 bytes per stage (A + B)
#define SMEM_MMA (3 * (int)STGB)  // 110592 bytes

template <int EPI, typename OutT, int K, int LDA, int LDB, int LDC>
__global__ void __launch_bounds__(256, 2)
mma_nt(const bf16* __restrict__ A, const bf16* __restrict__ B,
       OutT* __restrict__ C,
       long sA, long sB, long sC,
       const float* __restrict__ colBias,
       const float* __restrict__ rowBias,
       const float* __restrict__ gamma,
       const float* __restrict__ beta,
       const float* __restrict__ resid, long sR) {
    extern __shared__ char smem[];
    const uint32_t sbase = smem_u32(smem);
    const int tid = threadIdx.x;
    const int lane = tid & 31;
    const int warp = tid >> 5;
    const int z = blockIdx.z;
    const int m0 = blockIdx.y * 128;
    const int n0 = blockIdx.x * 128;
    const int wm = (warp & 1) * 64;   // warp row offset
    const int wn = (warp >> 1) * 32;  // warp col offset

    const char* gA = (const char*)(A + (long)z * sA) + (long)m0 * LDA * 2;
    const char* gB = (const char*)(B + (long)z * sB) + (long)n0 * LDB * 2;
    constexpr int nCh = K >> 6;

    // staging map: chunk = 128 rows x 128B per matrix = 1024 x 16B; 256 thr x 4
    int srow[4];
    uint32_t soff[4];
#pragma unroll
    for (int t = 0; t < 4; t++) {
        const int idx = tid + t * 256;
        srow[t] = idx >> 3;
        soff[t] = (uint32_t)(idx >> 3) * ROWB + (uint32_t)(idx & 7) * 16u;
    }

#define LOAD_CHUNK(buf, ch)                                                   \
    {                                                                         \
        const long cb = (long)(ch) << 7;                                      \
        const uint32_t s0 = sbase + (uint32_t)(buf) * STGB;                   \
        _Pragma("unroll") for (int t = 0; t < 4; t++) {                       \
            const long ko = cb + (soff[t] % ROWB);                            \
            cp16(s0 + soff[t], gA + (long)srow[t] * (LDA * 2) + ko);          \
            cp16(s0 + MATB + soff[t], gB + (long)srow[t] * (LDB * 2) + ko);   \
        }                                                                     \
        CP_COMMIT;                                                            \
    }

    // hoisted per-warp fragment smem offsets
    uint32_t Aoff[4], Boff[4];
#pragma unroll
    for (int mi = 0; mi < 4; mi++)
        Aoff[mi] = (uint32_t)(wm + mi * 16 + (lane & 15)) * ROWB +
                   (uint32_t)(lane >> 4) * 16u;
#pragma unroll
    for (int ni = 0; ni < 4; ni++)
        Boff[ni] = (uint32_t)(wn + ni * 8 + (lane & 7)) * ROWB +
                   (uint32_t)((lane >> 3) & 1) * 16u;

    float acc[4][4][4] = {};

    LOAD_CHUNK(0, 0);
    LOAD_CHUNK(1, 1);

    for (int c = 0; c < nCh; ++c) {
        if (c + 1 < nCh) { CP_WAIT1; } else { CP_WAIT0; }
        __syncthreads();
        if (c + 2 < nCh) {
            const int nb = (c + 2) % 3;
            LOAD_CHUNK(nb, c + 2);
        }
        const uint32_t sa = sbase + (uint32_t)(c % 3) * STGB;
        const uint32_t sb = sa + MATB;

        uint32_t afr[4][4], bfr0[4][2], bfr1[4][2];
        // preload B fragments for ks=0
#pragma unroll
        for (int ni = 0; ni < 4; ni++)
            ldmatrix_x2(bfr0[ni], sb + Boff[ni]);
#pragma unroll
        for (int ks = 0; ks < 4; ++ks) {
            // A fragments for this k-step
#pragma unroll
            for (int mi = 0; mi < 4; mi++)
                ldmatrix_x4(afr[mi], sa + Aoff[mi] + (uint32_t)ks * 32u);
            // prefetch B fragments for next k-step (double buffer)
            if (ks < 3) {
#pragma unroll
                for (int ni = 0; ni < 4; ni++)
                    ldmatrix_x2((ks & 1) ? bfr0[ni] : bfr1[ni],
                                sb + Boff[ni] + (uint32_t)(ks + 1) * 32u);
            }
            uint32_t(*bc)[2] = (ks & 1) ? bfr1 : bfr0;
#pragma unroll
            for (int mi = 0; mi < 4; mi++)
#pragma unroll
                for (int ni = 0; ni < 4; ni++)
                    mma_16816(acc[mi][ni], afr[mi], bc[ni]);
        }
    }

    // ---- epilogue ----
    const int tr = lane >> 2;
    const int tc = (lane & 3) * 2;
    const float bnscale = rsqrtf(1.0f + 1e-5f);
#pragma unroll
    for (int mi = 0; mi < 4; mi++) {
        const int r = m0 + wm + mi * 16 + tr;
#pragma unroll
        for (int ni = 0; ni < 4; ni++) {
            const int c = n0 + wn + ni * 8 + tc;
#pragma unroll
            for (int h = 0; h < 2; h++) {
                const int rr = r + h * 8;
                float v0 = acc[mi][ni][h * 2 + 0];
                float v1 = acc[mi][ni][h * 2 + 1];
                if (EPI == 1) {
                    v0 += colBias[c];
                    v1 += colBias[c + 1];
                } else if (EPI == 2) {
                    const float s = gamma[rr] * bnscale;
                    const float wb = rowBias[rr];
                    const float bt = beta[rr];
                    const float* rp = resid + (long)z * sR + (long)rr * LDC + c;
                    v0 = rp[0] + s * (v0 + wb) + bt;
                    v1 = rp[1] + s * (v1 + wb) + bt;
                }
                if constexpr (sizeof(OutT) == 2) {
                    __nv_bfloat162 p = __floats2bfloat162_rn(v0, v1);
                    *reinterpret_cast<__nv_bfloat162*>(
                        &((bf16*)(C + (long)z * sC))[(long)rr * LDC + c]) = p;
                } else {
                    float2 p = make_float2(v0, v1);
                    *reinterpret_cast<float2*>(
                        &((float*)(C + (long)z * sC))[(long)rr * LDC + c]) = p;
                }
            }
        }
    }
}

// ---------------------------------------------------------------------------
// Tiled transpose with dtype conversion: in (R,Cc) -> out (Cc,R) [ldOut], per z
// ---------------------------------------------------------------------------
__device__ __forceinline__ float ld_as_f(const float* p) { return *p; }
__device__ __forceinline__ float ld_as_f(const bf16* p) { return __bfloat162float(*p); }
__device__ __forceinline__ void st_from_f(float* p, float v) { *p = v; }
__device__ __forceinline__ void st_from_f(bf16* p, float v) { *p = __float2bfloat16(v); }

template <typename TI, typename TO>
__global__ void transpose_k(const TI* __restrict__ in, TO* __restrict__ out,
                            int R, int Cc, int ldOut, long sIn, long sOut) {
    __shared__ float tile[32][33];
    const TI* inb = in + (long)blockIdx.z * sIn;
    TO* outb = out + (long)blockIdx.z * sOut;
    const int c0 = blockIdx.x * 32;
    const int r0 = blockIdx.y * 32;
    const int tx = threadIdx.x, ty = threadIdx.y;
#pragma unroll
    for (int i = 0; i < 32; i += 8)
        tile[ty + i][tx] = ld_as_f(&inb[(long)(r0 + ty + i) * Cc + c0 + tx]);
    __syncthreads();
#pragma unroll
    for (int i = 0; i < 32; i += 8)
        st_from_f(&outb[(long)(c0 + ty + i) * ldOut + r0 + tx], tile[tx][ty + i]);
}

// ---------------------------------------------------------------------------
// fp32 -> bf16 convert for the 4 weight tensors in ONE launch (blockIdx.y picks)
// ---------------------------------------------------------------------------
__global__ void f2bf4_k(const float* __restrict__ w0, const float* __restrict__ w1,
                        const float* __restrict__ w2, const float* __restrict__ w3,
                        bf16* __restrict__ out, int n) {
    const int i = blockIdx.x * 256 + threadIdx.x;
    if (i >= n) return;
    const float* src = (blockIdx.y == 0) ? w0 : (blockIdx.y == 1) ? w1
                     : (blockIdx.y == 2) ? w2 : w3;
    out[(size_t)blockIdx.y * n + i] = __float2bfloat16(src[i]);
}

// concat th_b | ph_b | g_b into d_cbias (each CI_DIM long)
__global__ void catbias_k(const float* __restrict__ b0, const float* __restrict__ b1,
                          const float* __restrict__ b2, float* __restrict__ out) {
    const int i = blockIdx.x * 256 + threadIdx.x;
    if (i < CI_DIM) out[i] = b0[i];
    else if (i < 2 * CI_DIM) out[i] = b1[i - CI_DIM];
    else if (i < C3) out[i] = b2[i - 2 * CI_DIM];
}

// ---------------------------------------------------------------------------
// Fused 2x2x2 max pools (bf162-vectorized): scr2 (B,NPOS,C3) ->
//   z>>2==0: phi cols [512,1024)  -> d_phi (MPAD rows stride)
//   z>>2==1: g   cols [1024,1536) -> d_gmc (MPOS rows stride)
// ---------------------------------------------------------------------------
__global__ void __launch_bounds__(256) pool2_k(const bf16* __restrict__ scr2,
                                               bf16* __restrict__ phi,
                                               bf16* __restrict__ gmc) {
    const int which = blockIdx.z >> 2;
    const int b = blockIdx.z & 3;
    const int m = blockIdx.y;
    const int ci2 = threadIdx.x;           // handles cols 2*ci2, 2*ci2+1
    const int wp = m % WP;
    const int hp = (m / WP) % HP;
    const int tp = m / (WP * HP);
    const long n0 = (long)(2 * tp) * (H_DIM * W_DIM) + (long)(2 * hp) * W_DIM + 2 * wp;
    const bf16* base = scr2 + (long)b * NPOS * C3 +
                       (which ? 2 * CI_DIM : CI_DIM) + 2 * ci2;
    float v0 = -INFINITY, v1 = -INFINITY;
#pragma unroll
    for (int dt = 0; dt < 2; dt++)
#pragma unroll
        for (int dh = 0; dh < 2; dh++)
#pragma unroll
            for (int dw = 0; dw < 2; dw++) {
                const long n = n0 + dt * (H_DIM * W_DIM) + dh * W_DIM + dw;
                const __nv_bfloat162 v =
                    *reinterpret_cast<const __nv_bfloat162*>(base + n * C3);
                v0 = fmaxf(v0, __low2float(v));
                v1 = fmaxf(v1, __high2float(v));
            }
    const __nv_bfloat162 r = __floats2bfloat162_rn(v0, v1);
    if (which)
        *reinterpret_cast<__nv_bfloat162*>(
            gmc + ((long)b * MPOS + m) * CI_DIM + 2 * ci2) = r;
    else
        *reinterpret_cast<__nv_bfloat162*>(
            phi + ((long)b * MPAD + m) * CI_DIM + 2 * ci2) = r;
}

// ---------------------------------------------------------------------------
// In-place row softmax on bf16 logits (stride MPAD, MPOS valid); zeros the pads.
// ---------------------------------------------------------------------------
__global__ void __launch_bounds__(256) softmax_rows(bf16* __restrict__ f) {
    bf16* fr = f + (long)blockIdx.x * MPAD;
    const int t = threadIdx.x;
    float v[7];
    int cnt = 0;
    float mx = -1e30f;
    for (int i = t; i < MPOS; i += 256) {
        v[cnt] = __bfloat162float(fr[i]);
        mx = fmaxf(mx, v[cnt]);
        cnt++;
    }
    __shared__ float sred[8];
#pragma unroll
    for (int o = 16; o; o >>= 1) mx = fmaxf(mx, __shfl_xor_sync(0xffffffffu, mx, o));
    if ((t & 31) == 0) sred[t >> 5] = mx;
    __syncthreads();
    if (t < 32) {
        float m2 = (t < 8) ? sred[t] : -1e30f;
#pragma unroll
        for (int o = 4; o; o >>= 1) m2 = fmaxf(m2, __shfl_xor_sync(0xffffffffu, m2, o));
        if (t == 0) sred[0] = m2;
    }
    __syncthreads();
    mx = sred[0];
    float sum = 0.f;
    for (int j = 0; j < cnt; j++) {
        v[j] = __expf(v[j] - mx);
        sum += v[j];
    }
    __syncthreads();
#pragma unroll
    for (int o = 16; o; o >>= 1) sum += __shfl_xor_sync(0xffffffffu, sum, o);
    if ((t & 31) == 0) sred[t >> 5] = sum;
    __syncthreads();
    if (t < 32) {
        float s2 = (t < 8) ? sred[t] : 0.f;
#pragma unroll
        for (int o = 4; o; o >>= 1) s2 += __shfl_xor_sync(0xffffffffu, s2, o);
        if (t == 0) sred[0] = s2;
    }
    __syncthreads();
    const float inv = 1.0f / sred[0];
    int j = 0;
    for (int i = t; i < MPOS; i += 256) {
        fr[i] = __float2bfloat16(v[j] * inv);
        j++;
    }
    for (int i = MPOS + t; i < MPAD; i += 256) fr[i] = __float2bfloat16(0.f);
}

// ---------------------------------------------------------------------------
// Launch
// ---------------------------------------------------------------------------
extern "C" void kernel_launch(void* const* d_in, const int* in_sizes, int n_in,
                              void* d_out, int out_size) {
    (void)in_sizes; (void)n_in; (void)out_size;
    const float* x     = (const float*)d_in[0];
    const float* g_w   = (const float*)d_in[1];
    const float* g_b   = (const float*)d_in[2];
    const float* th_w  = (const float*)d_in[3];
    const float* th_b  = (const float*)d_in[4];
    const float* ph_w  = (const float*)d_in[5];
    const float* ph_b  = (const float*)d_in[6];
    const float* w_w   = (const float*)d_in[7];
    const float* w_b   = (const float*)d_in[8];
    const float* gamma = (const float*)d_in[9];
    const float* beta  = (const float*)d_in[10];
    float* out = (float*)d_out;

    bf16 *xT, *wbuf, *scr2, *phi, *gmc, *gcm, *fbuf, *ybuf;
    float* cbias;
    cudaGetSymbolAddress((void**)&xT, d_xT);
    cudaGetSymbolAddress((void**)&wbuf, d_wbuf);
    cudaGetSymbolAddress((void**)&cbias, d_cbias);
    cudaGetSymbolAddress((void**)&scr2, d_scr2);
    cudaGetSymbolAddress((void**)&phi, d_phi);
    cudaGetSymbolAddress((void**)&gmc, d_gmc);
    cudaGetSymbolAddress((void**)&gcm, d_gcm);
    cudaGetSymbolAddress((void**)&fbuf, d_fbuf);
    cudaGetSymbolAddress((void**)&ybuf, d_ybuf);

    // instantiations
    auto kConv = mma_nt<1, bf16, C_DIM, C_DIM, C_DIM, C3>;
    auto kF    = mma_nt<0, bf16, CI_DIM, C3, CI_DIM, MPAD>;
    auto kY    = mma_nt<0, bf16, MPAD, MPAD, MPAD, CI_DIM>;
    auto kW    = mma_nt<2, float, CI_DIM, CI_DIM, CI_DIM, NPOS>;
    cudaFuncSetAttribute(kConv, cudaFuncAttributeMaxDynamicSharedMemorySize, SMEM_MMA);
    cudaFuncSetAttribute(kF, cudaFuncAttributeMaxDynamicSharedMemorySize, SMEM_MMA);
    cudaFuncSetAttribute(kY, cudaFuncAttributeMaxDynamicSharedMemorySize, SMEM_MMA);
    cudaFuncSetAttribute(kW, cudaFuncAttributeMaxDynamicSharedMemorySize, SMEM_MMA);

    bf16* w_wb = wbuf + (size_t)3 * CI_DIM * C_DIM;  // (C, Ci)

    const long sX  = (long)C_DIM * NPOS;             // x batch stride
    const long sXT = (long)NPOS * C_DIM;
    const long sS2 = (long)NPOS * C3;
    const long sY  = (long)NPOS * CI_DIM;
    const long sPH = (long)MPAD * CI_DIM;
    const long sGC = (long)CI_DIM * MPAD;
    const long sF  = (long)NPOS * MPAD;

    const int nw = CI_DIM * C_DIM;
    // weights -> bf16: wbuf = [th | ph | g | w]; rows 0..1535 form fused conv W
    f2bf4_k<<<dim3((nw + 255) / 256, 4), 256>>>(th_w, ph_w, g_w, w_w, wbuf, nw);
    catbias_k<<<(C3 + 255) / 256, 256>>>(th_b, ph_b, g_b, cbias);

    // 1) x (B,C,N) -> xT bf16 (B,N,C)
    transpose_k<float, bf16><<<dim3(NPOS / 32, C_DIM / 32, BATCH), dim3(32, 8)>>>(
        x, xT, C_DIM, NPOS, C_DIM, sX, sXT);

    // 2) fused conv: scr2(N,1536) = xT @ [th|ph|g]^T + cbias
    kConv<<<dim3(C3 / 128, NPOS / 128, BATCH), 256, SMEM_MMA>>>(
        xT, wbuf, scr2, sXT, 0, sS2, cbias, nullptr, nullptr, nullptr, nullptr, 0);

    // 3) fused pools: phi cols [512,1024) -> d_phi; g cols [1024,1536) -> d_gmc
    pool2_k<<<dim3(1, MPOS, 2 * BATCH), 256>>>(scr2, phi, gmc);
    transpose_k<bf16, bf16><<<dim3(CI_DIM / 32, MPOS / 32, BATCH), dim3(32, 8)>>>(
        gmc, gcm, MPOS, CI_DIM, MPAD, (long)MPOS * CI_DIM, sGC);

    // 4) f = theta @ phi^T -> bf16 logits (N,Mpad); theta = scr2 cols [0,512)
    kF<<<dim3(MPAD / 128, NPOS / 128, BATCH), 256, SMEM_MMA>>>(
        scr2, phi, fbuf, sS2, sPH, sF, nullptr, nullptr, nullptr, nullptr,
        nullptr, 0);

    // 5) in-place softmax (bf16 logits -> bf16 probs, zeros in pads)
    softmax_rows<<<BATCH * NPOS, 256>>>(fbuf);

    // 6) y = p @ g : (N,Mpad)x(Ci,Mpad)^T -> bf16 (N,Ci)
    kY<<<dim3(CI_DIM / 128, NPOS / 128, BATCH), 256, SMEM_MMA>>>(
        fbuf, gcm, ybuf, sF, sGC, sY, nullptr, nullptr, nullptr, nullptr,
        nullptr, 0);

    // 7) out(C,N) = x + scale*(w_w @ y^T + w_b) + beta
    kW<<<dim3(NPOS / 128, C_DIM / 128, BATCH), 256, SMEM_MMA>>>(
        w_wb, ybuf, out, 0, sY, sX, nullptr, w_b, gamma, beta, x, sX);
}